// round 1
// baseline (speedup 1.0000x reference)
#include <cuda_runtime.h>
#include <cstdint>
#include <cstddef>

// Problem constants
#define BB    2
#define NN    2048      // nodes
#define FF    32        // feature cols
#define DROWS 8192      // R*LEV*N
#define DCOLS 2049      // N+1
#define M1    6144      // rows of x_shrink per batch
#define KO    2049      // out rows per batch

// Tiling
#define TR    64        // rows per block tile
#define KC    32        // k-chunk
#define NTHR  256

#define THR_SHRINK 0.086289726f   // sqrt(2*ln(2048))/sqrt(2048)

// Scratch (static device globals: allocation-free)
__device__ float g_xw[BB * NN * FF];            // x @ W       : [b][n][c]
__device__ float g_xs[BB * M1 * FF];            // x_shrink    : [b][m][c]
__device__ float g_part[2 * BB * KO * FF];      // split-K partials for GEMM-C

// ---------------- helpers ----------------
__device__ __forceinline__ void cpa4(uint32_t dst, const float* src, int bytes) {
    asm volatile("cp.async.ca.shared.global [%0], [%1], 4, %2;"
                 :: "r"(dst), "l"(src), "r"(bytes));
}
__device__ __forceinline__ void cpa_commit() { asm volatile("cp.async.commit_group;"); }
template <int N> __device__ __forceinline__ void cpa_wait() {
    asm volatile("cp.async.wait_group %0;" :: "n"(N));
}
__device__ __forceinline__ unsigned long long ffma2(unsigned long long a,
                                                    unsigned long long b,
                                                    unsigned long long c) {
    unsigned long long d;
    asm("fma.rn.f32x2 %0, %1, %2, %3;" : "=l"(d) : "l"(a), "l"(b), "l"(c));
    return d;
}
__device__ __forceinline__ unsigned long long splat2(float v) {
    unsigned long long d;
    unsigned u = __float_as_uint(v);
    asm("mov.b64 %0, {%1, %1};" : "=l"(d) : "r"(u));
    return d;
}
__device__ __forceinline__ void unpack2(unsigned long long a, float& lo, float& hi) {
    unsigned l, h;
    asm("mov.b64 {%0, %1}, %2;" : "=r"(l), "=r"(h) : "l"(a));
    lo = __uint_as_float(l);
    hi = __uint_as_float(h);
}

// ---------------- kernel 1: xw = x @ W ----------------
__global__ void k_xw(const float* __restrict__ x, const float* __restrict__ w) {
    __shared__ float sW[FF * FF];
    int tid = threadIdx.x;
    for (int i = tid; i < FF * FF; i += NTHR) sW[i] = w[i];
    __syncthreads();
    int warp = tid >> 5, lane = tid & 31;
    int row = blockIdx.x * 8 + warp;           // 0..4095 = b*2048 + n
    float xv = x[(size_t)row * FF + lane];
    float acc = 0.f;
#pragma unroll
    for (int f = 0; f < FF; f++)
        acc = fmaf(__shfl_sync(0xffffffffu, xv, f), sW[f * FF + lane], acc);
    g_xw[(size_t)row * FF + lane] = acc;
}

// ---------------- kernel 2: GEMM-B  (xc rows 2048.. -> x_shrink) ----------------
__global__ __launch_bounds__(NTHR, 2)
void k_gemmB(const float* __restrict__ dl, const float* __restrict__ filt) {
    __shared__ __align__(16) float sA[2][TR][KC + 1];
    __shared__ __align__(16) float sB[2][KC][FF];

    int tid = threadIdx.x;
    int bx = blockIdx.x;                 // 0..191
    int b  = bx / (M1 / TR);             // /96
    int m0 = (bx % (M1 / TR)) * TR;      // 0..6080

    const float* Abase = dl + (size_t)b * DROWS * DCOLS + (size_t)2048 * DCOLS + 1;
    const float* Bbase = g_xw + (size_t)b * NN * FF;

    uint32_t sA_u = (uint32_t)__cvta_generic_to_shared(&sA[0][0][0]);
    uint32_t sB_u = (uint32_t)__cvta_generic_to_shared(&sB[0][0][0]);

    auto load_chunk = [&](int st, int k0) {
#pragma unroll
        for (int j = 0; j < 8; j++) {
            int idx = tid + j * NTHR;            // 0..2047
            int r = idx >> 5, k = idx & 31;
            const float* src = Abase + (size_t)(m0 + r) * DCOLS + (k0 + k);
            cpa4(sA_u + (uint32_t)(((st * TR + r) * (KC + 1) + k) * 4), src, 4);
        }
#pragma unroll
        for (int j = 0; j < 4; j++) {
            int idx = tid + j * NTHR;            // 0..1023
            int n = idx >> 5, c = idx & 31;
            cpa4(sB_u + (uint32_t)(((st * KC + n) * FF + c) * 4),
                 Bbase + (size_t)(k0 + n) * FF + c, 4);
        }
        cpa_commit();
    };

    int row = tid >> 2;       // 0..63
    int cg  = tid & 3;        // 8 cols each

    unsigned long long a0 = 0, a1 = 0, a2 = 0, a3 = 0;

    load_chunk(0, 0);
    const int NCH = NN / KC;  // 64
    for (int ch = 0; ch < NCH; ch++) {
        int st = ch & 1;
        if (ch + 1 < NCH) { load_chunk(st ^ 1, (ch + 1) * KC); cpa_wait<1>(); }
        else              { cpa_wait<0>(); }
        __syncthreads();
        const float* Ar = &sA[st][row][0];
        const float* Bc = &sB[st][0][cg * 8];
#pragma unroll
        for (int n = 0; n < KC; n++) {
            unsigned long long d2 = splat2(Ar[n]);
            ulonglong2 w01 = *(const ulonglong2*)(Bc + n * FF);
            ulonglong2 w23 = *(const ulonglong2*)(Bc + n * FF + 4);
            a0 = ffma2(d2, w01.x, a0);
            a1 = ffma2(d2, w01.y, a1);
            a2 = ffma2(d2, w23.x, a2);
            a3 = ffma2(d2, w23.y, a3);
        }
        __syncthreads();
    }

    // epilogue: filt scale + soft-threshold on high rows, write x_shrink
    int mr = m0 + row;                       // 0..6143
    float fv = filt[2048 + mr];
    bool sh = (mr >= 2048);
    float v[8];
    unpack2(a0, v[0], v[1]);
    unpack2(a1, v[2], v[3]);
    unpack2(a2, v[4], v[5]);
    unpack2(a3, v[6], v[7]);
#pragma unroll
    for (int i = 0; i < 8; i++) {
        float t = v[i] * fv;
        if (sh) t = copysignf(fmaxf(fabsf(t) - THR_SHRINK, 0.0f), t);
        v[i] = t;
    }
    float4* dst = (float4*)&g_xs[((size_t)b * M1 + mr) * FF + cg * 8];
    dst[0] = make_float4(v[0], v[1], v[2], v[3]);
    dst[1] = make_float4(v[4], v[5], v[6], v[7]);
}

// ---------------- kernel 3: GEMM-C  (y2 @ x_shrink, split-K=2) ----------------
__global__ __launch_bounds__(NTHR, 2)
void k_gemmC(const float* __restrict__ dl) {
    __shared__ __align__(16) float sA[2][TR][KC + 1];
    __shared__ __align__(16) float sB[2][KC][FF];

    int tid = threadIdx.x;
    int bx = blockIdx.x;                 // 0..131
    int b  = bx / 66;
    int r2 = bx % 66;
    int ks = r2 / 33;
    int mt = r2 % 33;
    int m0 = mt * TR;                    // out-row tile base (valid rows < 2049)
    int kbase = ks * (M1 / 2);           // 0 or 3072

    const float* Abase = dl + (size_t)b * DROWS * DCOLS + (size_t)2048 * DCOLS;
    const float* Bbase = g_xs + (size_t)b * M1 * FF;

    uint32_t sA_u = (uint32_t)__cvta_generic_to_shared(&sA[0][0][0]);
    uint32_t sB_u = (uint32_t)__cvta_generic_to_shared(&sB[0][0][0]);

    auto load_chunk = [&](int st, int k0) {
#pragma unroll
        for (int j = 0; j < 8; j++) {
            int idx = tid + j * NTHR;
            int r = idx >> 5, k = idx & 31;
            int grow = m0 + r;
            bool valid = (grow < KO);
            const float* src = valid
                ? Abase + (size_t)grow * M1 + (kbase + k0 + k)
                : Abase;
            cpa4(sA_u + (uint32_t)(((st * TR + r) * (KC + 1) + k) * 4), src, valid ? 4 : 0);
        }
#pragma unroll
        for (int j = 0; j < 4; j++) {
            int idx = tid + j * NTHR;
            int n = idx >> 5, c = idx & 31;
            cpa4(sB_u + (uint32_t)(((st * KC + n) * FF + c) * 4),
                 Bbase + (size_t)(kbase + k0 + n) * FF + c, 4);
        }
        cpa_commit();
    };

    int row = tid >> 2;
    int cg  = tid & 3;

    unsigned long long a0 = 0, a1 = 0, a2 = 0, a3 = 0;

    load_chunk(0, 0);
    const int NCH = (M1 / 2) / KC;       // 96
    for (int ch = 0; ch < NCH; ch++) {
        int st = ch & 1;
        if (ch + 1 < NCH) { load_chunk(st ^ 1, (ch + 1) * KC); cpa_wait<1>(); }
        else              { cpa_wait<0>(); }
        __syncthreads();
        const float* Ar = &sA[st][row][0];
        const float* Bc = &sB[st][0][cg * 8];
#pragma unroll
        for (int n = 0; n < KC; n++) {
            unsigned long long d2 = splat2(Ar[n]);
            ulonglong2 w01 = *(const ulonglong2*)(Bc + n * FF);
            ulonglong2 w23 = *(const ulonglong2*)(Bc + n * FF + 4);
            a0 = ffma2(d2, w01.x, a0);
            a1 = ffma2(d2, w01.y, a1);
            a2 = ffma2(d2, w23.x, a2);
            a3 = ffma2(d2, w23.y, a3);
        }
        __syncthreads();
    }

    int grow = m0 + row;
    if (grow < KO) {
        float v[8];
        unpack2(a0, v[0], v[1]);
        unpack2(a1, v[2], v[3]);
        unpack2(a2, v[4], v[5]);
        unpack2(a3, v[6], v[7]);
        float4* dst = (float4*)&g_part[((size_t)(ks * BB + b) * KO + grow) * FF + cg * 8];
        dst[0] = make_float4(v[0], v[1], v[2], v[3]);
        dst[1] = make_float4(v[4], v[5], v[6], v[7]);
    }
}

// ---------------- kernel 4: combine split-K partials + bias ----------------
__global__ void k_combine(const float* __restrict__ bias, float* __restrict__ out) {
    int idx = blockIdx.x * NTHR + threadIdx.x;
    const int TOT = BB * KO * FF;        // 131136
    if (idx < TOT) {
        int c = idx & 31;
        out[idx] = bias[c] + g_part[idx] + g_part[TOT + idx];
    }
}

// ---------------- launch ----------------
extern "C" void kernel_launch(void* const* d_in, const int* in_sizes, int n_in,
                              void* d_out, int out_size) {
    (void)in_sizes; (void)n_in; (void)out_size;
    const float* x    = (const float*)d_in[0];
    const float* dl   = (const float*)d_in[1];
    const float* w    = (const float*)d_in[2];
    const float* filt = (const float*)d_in[3];
    const float* bias = (const float*)d_in[4];
    float* out = (float*)d_out;

    k_xw    <<<(BB * NN) / 8, NTHR>>>(x, w);
    k_gemmB <<<BB * (M1 / TR), NTHR>>>(dl, filt);
    k_gemmC <<<BB * 2 * 33, NTHR>>>(dl);
    k_combine<<<(BB * KO * FF + NTHR - 1) / NTHR, NTHR>>>(bias, out);
}

// round 2
// speedup vs baseline: 1.0571x; 1.0571x over previous
#include <cuda_runtime.h>
#include <cstdint>
#include <cstddef>

// Problem constants
#define BB    2
#define NN    2048      // nodes
#define FF    32        // feature cols
#define DROWS 8192      // R*LEV*N
#define DCOLS 2049      // N+1
#define M1    6144      // rows of x_shrink per batch
#define KO    2049      // out rows per batch

// Tiling
#define TR    64        // rows per block tile
#define KC    32        // k-chunk
#define NTHR  256

#define THR_SHRINK 0.086289726f   // sqrt(2*ln(2048))/sqrt(2048)

// Scratch (static device globals: allocation-free)
__device__ float g_xw[BB * NN * FF];            // x @ W       : [b][n][c]
__device__ float g_xs[BB * M1 * FF];            // x_shrink    : [b][m][c]
__device__ float g_part[2 * BB * KO * FF];      // split-K partials for GEMM-C

// ---------------- helpers ----------------
__device__ __forceinline__ void cpa4(uint32_t dst, const float* src, int bytes) {
    asm volatile("cp.async.ca.shared.global [%0], [%1], 4, %2;"
                 :: "r"(dst), "l"(src), "r"(bytes));
}
__device__ __forceinline__ void cpa_commit() { asm volatile("cp.async.commit_group;"); }
template <int N> __device__ __forceinline__ void cpa_wait() {
    asm volatile("cp.async.wait_group %0;" :: "n"(N));
}
__device__ __forceinline__ unsigned long long ffma2(unsigned long long a,
                                                    unsigned long long b,
                                                    unsigned long long c) {
    unsigned long long d;
    asm("fma.rn.f32x2 %0, %1, %2, %3;" : "=l"(d) : "l"(a), "l"(b), "l"(c));
    return d;
}
__device__ __forceinline__ unsigned long long splat2(float v) {
    unsigned long long d;
    unsigned u = __float_as_uint(v);
    asm("mov.b64 %0, {%1, %1};" : "=l"(d) : "r"(u));
    return d;
}
__device__ __forceinline__ void unpack2(unsigned long long a, float& lo, float& hi) {
    unsigned l, h;
    asm("mov.b64 {%0, %1}, %2;" : "=r"(l), "=r"(h) : "l"(a));
    lo = __uint_as_float(l);
    hi = __uint_as_float(h);
}

// ---------------- kernel 1: xw = x @ W ----------------
__global__ void k_xw(const float* __restrict__ x, const float* __restrict__ w) {
    __shared__ float sW[FF * FF];
    int tid = threadIdx.x;
    for (int i = tid; i < FF * FF; i += NTHR) sW[i] = w[i];
    __syncthreads();
    int warp = tid >> 5, lane = tid & 31;
    int row = blockIdx.x * 8 + warp;           // 0..4095 = b*2048 + n
    float xv = x[(size_t)row * FF + lane];
    float acc = 0.f;
#pragma unroll
    for (int f = 0; f < FF; f++)
        acc = fmaf(__shfl_sync(0xffffffffu, xv, f), sW[f * FF + lane], acc);
    g_xw[(size_t)row * FF + lane] = acc;
}

// ---------------- kernel 2: GEMM-B  (xc rows 2048.. -> x_shrink) ----------------
__global__ __launch_bounds__(NTHR, 2)
void k_gemmB(const float* __restrict__ dl, const float* __restrict__ filt) {
    __shared__ __align__(16) float sA[2][TR][KC + 1];
    __shared__ __align__(16) float sB[2][KC][FF];

    int tid = threadIdx.x;
    int bx = blockIdx.x;                 // 0..191
    int b  = bx / (M1 / TR);             // /96
    int m0 = (bx % (M1 / TR)) * TR;      // 0..6080

    const float* Abase = dl + (size_t)b * DROWS * DCOLS + (size_t)2048 * DCOLS + 1;
    const float* Bbase = g_xw + (size_t)b * NN * FF;

    uint32_t sA_u = (uint32_t)__cvta_generic_to_shared(&sA[0][0][0]);
    uint32_t sB_u = (uint32_t)__cvta_generic_to_shared(&sB[0][0][0]);

    auto load_chunk = [&](int st, int k0) {
#pragma unroll
        for (int j = 0; j < 8; j++) {
            int idx = tid + j * NTHR;            // 0..2047
            int r = idx >> 5, k = idx & 31;
            const float* src = Abase + (size_t)(m0 + r) * DCOLS + (k0 + k);
            cpa4(sA_u + (uint32_t)(((st * TR + r) * (KC + 1) + k) * 4), src, 4);
        }
#pragma unroll
        for (int j = 0; j < 4; j++) {
            int idx = tid + j * NTHR;            // 0..1023
            int n = idx >> 5, c = idx & 31;
            cpa4(sB_u + (uint32_t)(((st * KC + n) * FF + c) * 4),
                 Bbase + (size_t)(k0 + n) * FF + c, 4);
        }
        cpa_commit();
    };

    int row = tid >> 2;       // 0..63
    int cg  = tid & 3;        // 8 cols each

    unsigned long long a0 = 0, a1 = 0, a2 = 0, a3 = 0;

    load_chunk(0, 0);
    const int NCH = NN / KC;  // 64
    for (int ch = 0; ch < NCH; ch++) {
        int st = ch & 1;
        if (ch + 1 < NCH) { load_chunk(st ^ 1, (ch + 1) * KC); cpa_wait<1>(); }
        else              { cpa_wait<0>(); }
        __syncthreads();
        const float* Ar = &sA[st][row][0];
        const float* Bc = &sB[st][0][cg * 8];
#pragma unroll
        for (int n = 0; n < KC; n++) {
            unsigned long long d2 = splat2(Ar[n]);
            ulonglong2 w01 = *(const ulonglong2*)(Bc + n * FF);
            ulonglong2 w23 = *(const ulonglong2*)(Bc + n * FF + 4);
            a0 = ffma2(d2, w01.x, a0);
            a1 = ffma2(d2, w01.y, a1);
            a2 = ffma2(d2, w23.x, a2);
            a3 = ffma2(d2, w23.y, a3);
        }
        __syncthreads();
    }

    // epilogue: filt scale + soft-threshold on high rows, write x_shrink
    int mr = m0 + row;                       // 0..6143
    float fv = filt[2048 + mr];
    bool sh = (mr >= 2048);
    float v[8];
    unpack2(a0, v[0], v[1]);
    unpack2(a1, v[2], v[3]);
    unpack2(a2, v[4], v[5]);
    unpack2(a3, v[6], v[7]);
#pragma unroll
    for (int i = 0; i < 8; i++) {
        float t = v[i] * fv;
        if (sh) t = copysignf(fmaxf(fabsf(t) - THR_SHRINK, 0.0f), t);
        v[i] = t;
    }
    float4* dst = (float4*)&g_xs[((size_t)b * M1 + mr) * FF + cg * 8];
    dst[0] = make_float4(v[0], v[1], v[2], v[3]);
    dst[1] = make_float4(v[4], v[5], v[6], v[7]);
}

// ---------------- kernel 3: GEMM-C  (y2 @ x_shrink, split-K=2) ----------------
__global__ __launch_bounds__(NTHR, 2)
void k_gemmC(const float* __restrict__ dl) {
    __shared__ __align__(16) float sA[2][TR][KC + 1];
    __shared__ __align__(16) float sB[2][KC][FF];

    int tid = threadIdx.x;
    int bx = blockIdx.x;                 // 0..131
    int b  = bx / 66;
    int r2 = bx % 66;
    int ks = r2 / 33;
    int mt = r2 % 33;
    int m0 = mt * TR;                    // out-row tile base (valid rows < 2049)
    int kbase = ks * (M1 / 2);           // 0 or 3072

    const float* Abase = dl + (size_t)b * DROWS * DCOLS + (size_t)2048 * DCOLS;
    const float* Bbase = g_xs + (size_t)b * M1 * FF;

    uint32_t sA_u = (uint32_t)__cvta_generic_to_shared(&sA[0][0][0]);
    uint32_t sB_u = (uint32_t)__cvta_generic_to_shared(&sB[0][0][0]);

    auto load_chunk = [&](int st, int k0) {
#pragma unroll
        for (int j = 0; j < 8; j++) {
            int idx = tid + j * NTHR;
            int r = idx >> 5, k = idx & 31;
            int grow = m0 + r;
            bool valid = (grow < KO);
            const float* src = valid
                ? Abase + (size_t)grow * M1 + (kbase + k0 + k)
                : Abase;
            cpa4(sA_u + (uint32_t)(((st * TR + r) * (KC + 1) + k) * 4), src, valid ? 4 : 0);
        }
#pragma unroll
        for (int j = 0; j < 4; j++) {
            int idx = tid + j * NTHR;
            int n = idx >> 5, c = idx & 31;
            cpa4(sB_u + (uint32_t)(((st * KC + n) * FF + c) * 4),
                 Bbase + (size_t)(kbase + k0 + n) * FF + c, 4);
        }
        cpa_commit();
    };

    int row = tid >> 2;
    int cg  = tid & 3;

    unsigned long long a0 = 0, a1 = 0, a2 = 0, a3 = 0;

    load_chunk(0, 0);
    const int NCH = (M1 / 2) / KC;       // 96
    for (int ch = 0; ch < NCH; ch++) {
        int st = ch & 1;
        if (ch + 1 < NCH) { load_chunk(st ^ 1, (ch + 1) * KC); cpa_wait<1>(); }
        else              { cpa_wait<0>(); }
        __syncthreads();
        const float* Ar = &sA[st][row][0];
        const float* Bc = &sB[st][0][cg * 8];
#pragma unroll
        for (int n = 0; n < KC; n++) {
            unsigned long long d2 = splat2(Ar[n]);
            ulonglong2 w01 = *(const ulonglong2*)(Bc + n * FF);
            ulonglong2 w23 = *(const ulonglong2*)(Bc + n * FF + 4);
            a0 = ffma2(d2, w01.x, a0);
            a1 = ffma2(d2, w01.y, a1);
            a2 = ffma2(d2, w23.x, a2);
            a3 = ffma2(d2, w23.y, a3);
        }
        __syncthreads();
    }

    int grow = m0 + row;
    if (grow < KO) {
        float v[8];
        unpack2(a0, v[0], v[1]);
        unpack2(a1, v[2], v[3]);
        unpack2(a2, v[4], v[5]);
        unpack2(a3, v[6], v[7]);
        float4* dst = (float4*)&g_part[((size_t)(ks * BB + b) * KO + grow) * FF + cg * 8];
        dst[0] = make_float4(v[0], v[1], v[2], v[3]);
        dst[1] = make_float4(v[4], v[5], v[6], v[7]);
    }
}

// ---------------- kernel 4: combine split-K partials + bias ----------------
__global__ void k_combine(const float* __restrict__ bias, float* __restrict__ out) {
    int idx = blockIdx.x * NTHR + threadIdx.x;
    const int TOT = BB * KO * FF;        // 131136
    if (idx < TOT) {
        int c = idx & 31;
        out[idx] = bias[c] + g_part[idx] + g_part[TOT + idx];
    }
}

// ---------------- launch ----------------
extern "C" void kernel_launch(void* const* d_in, const int* in_sizes, int n_in,
                              void* d_out, int out_size) {
    (void)in_sizes; (void)n_in; (void)out_size;
    const float* x    = (const float*)d_in[0];
    const float* dl   = (const float*)d_in[1];
    const float* w    = (const float*)d_in[2];
    const float* filt = (const float*)d_in[3];
    const float* bias = (const float*)d_in[4];
    float* out = (float*)d_out;

    k_xw    <<<(BB * NN) / 8, NTHR>>>(x, w);
    k_gemmB <<<BB * (M1 / TR), NTHR>>>(dl, filt);
    k_gemmC <<<BB * 2 * 33, NTHR>>>(dl);
    k_combine<<<(BB * KO * FF + NTHR - 1) / NTHR, NTHR>>>(bias, out);
}

// round 4
// speedup vs baseline: 3.6090x; 3.4140x over previous
#include <cuda_runtime.h>
#include <cuda_bf16.h>
#include <cstdint>
#include <cstddef>

#define BB 2
#define NN 2048
#define FF 32
#define DROWS 8192
#define DCOLS 2049
#define M1 6144
#define KO 2049
#define NTHR 256
#define THRS 0.086289726f
#define TOTC (BB*KO*FF)

// smem: A f32 [2][128][36] ; B bf16 [2][hi/lo][32][40]
#define A_ST(st)  ((uint32_t)(st)*18432u)
#define BH_ST(st) (36864u + (uint32_t)(st)*5120u)
#define BL_ST(st) (36864u + (uint32_t)(st)*5120u + 2560u)
#define SM_TOT 47104

__device__ __align__(16) uint16_t g_xwT_h[BB*FF*NN];
__device__ __align__(16) uint16_t g_xwT_l[BB*FF*NN];
__device__ __align__(16) uint16_t g_xsT_h[BB*FF*M1];
__device__ __align__(16) uint16_t g_xsT_l[BB*FF*M1];
__device__ float g_part[4*TOTC];

__device__ __forceinline__ void cpa16(uint32_t d, const void* s, int vs){
    asm volatile("cp.async.ca.shared.global [%0], [%1], 16, %2;" :: "r"(d), "l"(s), "r"(vs));
}
__device__ __forceinline__ void cpa_commit(){ asm volatile("cp.async.commit_group;"); }
template <int N> __device__ __forceinline__ void cpa_wait(){
    asm volatile("cp.async.wait_group %0;" :: "n"(N));
}
__device__ __forceinline__ uint32_t packbf(float lo, float hi){
    uint32_t r; asm("cvt.rn.bf16x2.f32 %0, %1, %2;" : "=r"(r) : "f"(hi), "f"(lo)); return r;
}
// split two f32 into hi-bf16x2 and lo-bf16x2
__device__ __forceinline__ void split2(float x, float y, uint32_t& h, uint32_t& l){
    h = packbf(x, y);
    float hx = __uint_as_float(h << 16);
    float hy = __uint_as_float(h & 0xffff0000u);
    l = packbf(x - hx, y - hy);
}
__device__ __forceinline__ void mma_bf16(float* c, const uint32_t* a, uint32_t b0, uint32_t b1){
    asm("mma.sync.aligned.m16n8k16.row.col.f32.bf16.bf16.f32 "
        "{%0,%1,%2,%3},{%4,%5,%6,%7},{%8,%9},{%0,%1,%2,%3};"
        : "+f"(c[0]), "+f"(c[1]), "+f"(c[2]), "+f"(c[3])
        : "r"(a[0]), "r"(a[1]), "r"(a[2]), "r"(a[3]), "r"(b0), "r"(b1));
}

// ---------- kernel 1: xw = x@W -> bf16-split transposed [b][c][n] ----------
__global__ void k_xw(const float* __restrict__ x, const float* __restrict__ w){
    __shared__ float sW[FF*FF];
    __shared__ float sT[FF*65];
    int tid = threadIdx.x, wid = tid>>5, lane = tid&31;
    for (int i = tid; i < FF*FF; i += NTHR) sW[i] = w[i];
    __syncthreads();
    float wreg[FF];
#pragma unroll
    for (int f = 0; f < FF; f++) wreg[f] = sW[f*FF + lane];
    int R0 = blockIdx.x * 64;
    float acc[8];
#pragma unroll
    for (int i = 0; i < 8; i++){
        int row = R0 + wid*8 + i;
        float xv = x[(size_t)row*FF + lane];
        float a = 0.f;
#pragma unroll
        for (int f = 0; f < FF; f++)
            a = fmaf(__shfl_sync(0xffffffffu, xv, f), wreg[f], a);
        acc[i] = a;
    }
#pragma unroll
    for (int i = 0; i < 8; i++) sT[lane*65 + wid*8 + i] = acc[i];
    __syncthreads();
    int c = tid>>3, i8 = tid&7;
    int b = R0 >> 11, nloc = (R0 & 2047) + i8*8;
    uint32_t h[4], l[4];
#pragma unroll
    for (int j = 0; j < 4; j++){
        float t0 = sT[c*65 + i8*8 + 2*j], t1 = sT[c*65 + i8*8 + 2*j + 1];
        split2(t0, t1, h[j], l[j]);
    }
    size_t off = ((size_t)b*FF + c)*NN + nloc;
    *(uint4*)(g_xwT_h + off) = make_uint4(h[0], h[1], h[2], h[3]);
    *(uint4*)(g_xwT_l + off) = make_uint4(l[0], l[1], l[2], l[3]);
}

// ---------- unified HMMA GEMM ----------
// IS_C=false: D[m][c] = sum_k dl[2048+m][1+k] * xw[k][c]       (96 blocks, K=2048)
// IS_C=true : D[g][c] = sum_k y2[g][kb+k]   * xs[kb+k][c]      (136 blocks, split-K=4)
template <bool IS_C>
__global__ __launch_bounds__(NTHR, 2)
void k_gemm(const float* __restrict__ dl, const float* __restrict__ filt){
    __shared__ __align__(16) char smbuf[SM_TOT];
    uint32_t smb = (uint32_t)__cvta_generic_to_shared(smbuf);

    int tid = threadIdx.x, w = tid>>5, lane = tid&31;
    int g = lane>>2, tg = lane&3;
    int bx = blockIdx.x;

    int b, m0, kbase, ks;
    const float* Ab;
    const uint16_t *BTh, *BTl;
    constexpr int NCH = IS_C ? 48 : 64;
    constexpr int BK  = IS_C ? M1 : NN;
    if (!IS_C){
        b = bx/48; m0 = (bx%48)*128; kbase = 0; ks = 0;
        BTh = g_xwT_h + (size_t)b*FF*NN; BTl = g_xwT_l + (size_t)b*FF*NN;
    } else {
        b = bx/68; int rem = bx%68; ks = rem/17; m0 = (rem%17)*128; kbase = ks*1536;
        BTh = g_xsT_h + (size_t)b*FF*M1; BTl = g_xsT_l + (size_t)b*FF*M1;
    }
    Ab = dl + (size_t)b*DROWS*DCOLS + (size_t)2048*DCOLS;

    auto prefetch = [&](int ch, int st){
        int k0 = kbase + ch*32;
        if (!IS_C){
#pragma unroll
            for (int j = 0; j < 5; j++){
                int idx = tid + j*NTHR;
                if (idx < 1152){
                    int r = (idx*7282)>>16;
                    int q = idx - r*9;
                    int s = (r + 1) & 3;
                    const float* src = Ab + (size_t)(m0+r)*DCOLS + (k0 + 1 - s) + q*4;
                    int vs = (q < 8 || s) ? 16 : 0;
                    cpa16(smb + A_ST(st) + (uint32_t)(r*144 + q*16), src, vs);
                }
            }
        } else {
#pragma unroll
            for (int j = 0; j < 4; j++){
                int idx = tid + j*NTHR;
                int r = idx>>3, q = idx&7;
                int grow = m0 + r;
                const float* src = Ab + (size_t)(grow < KO ? grow : 0)*M1 + k0 + q*4;
                cpa16(smb + A_ST(st) + (uint32_t)(r*144 + q*16), src, 16);
            }
        }
        {
            int sel = tid>>7, rest = tid&127;
            int c = rest>>2, q = rest&3;
            const uint16_t* src = (sel ? BTl : BTh) + (size_t)c*BK + k0 + q*8;
            cpa16(smb + (sel ? BL_ST(st) : BH_ST(st)) + (uint32_t)(c*80 + q*16), src, 16);
        }
        cpa_commit();
    };

    float acc[4][4] = {};
    int r0 = 16*w + g;
    int sft = IS_C ? 0 : ((r0 + 1) & 3);

    prefetch(0, 0);
    for (int ch = 0; ch < NCH; ch++){
        int st = ch & 1;
        if (ch + 1 < NCH){ prefetch(ch+1, st^1); cpa_wait<1>(); }
        else             { cpa_wait<0>(); }
        __syncthreads();

        const float* As = (const float*)(smbuf + A_ST(st));
        const char* Bh = smbuf + BH_ST(st);
        const char* Bl = smbuf + BL_ST(st);
#pragma unroll
        for (int k2 = 0; k2 < 2; k2++){
            int kk = k2*16;
            const float* p0 = As + r0*36 + sft + kk + 2*tg;
            const float* p1 = p0 + 8*36;
            float f0 = p0[0], f1 = p0[1], f2 = p0[8], f3 = p0[9];
            float f4 = p1[0], f5 = p1[1], f6 = p1[8], f7 = p1[9];
            uint32_t ah[4], al[4];
            split2(f0, f1, ah[0], al[0]);
            split2(f4, f5, ah[1], al[1]);
            split2(f2, f3, ah[2], al[2]);
            split2(f6, f7, ah[3], al[3]);
#pragma unroll
            for (int nt = 0; nt < 4; nt++){
                int bo = (nt*8 + g)*80 + (kk + 2*tg)*2;
                uint32_t bh0 = *(const uint32_t*)(Bh + bo);
                uint32_t bh1 = *(const uint32_t*)(Bh + bo + 16);
                uint32_t bl0 = *(const uint32_t*)(Bl + bo);
                uint32_t bl1 = *(const uint32_t*)(Bl + bo + 16);
                mma_bf16(acc[nt], ah, bh0, bh1);
                mma_bf16(acc[nt], ah, bl0, bl1);
                mma_bf16(acc[nt], al, bh0, bh1);
            }
        }
        __syncthreads();
    }

    if (!IS_C){
        // stage accums in smem f32 [128][36], then coalesced bf16-split transposed store
        float* Ep = (float*)smbuf;
#pragma unroll
        for (int nt = 0; nt < 4; nt++){
            int c0 = nt*8 + 2*tg;
            *(float2*)(Ep + r0*36 + c0)       = make_float2(acc[nt][0], acc[nt][1]);
            *(float2*)(Ep + (r0+8)*36 + c0)   = make_float2(acc[nt][2], acc[nt][3]);
        }
        __syncthreads();
        int c = tid & 31, seg = tid >> 5;
        int mb = seg * 16;
        uint32_t h[8], l[8];
#pragma unroll
        for (int j = 0; j < 8; j++){
            int i0 = mb + 2*j, i1 = i0 + 1;
            int mr0 = m0 + i0, mr1 = m0 + i1;
            float t0 = Ep[i0*36 + c] * filt[2048 + mr0];
            float t1 = Ep[i1*36 + c] * filt[2048 + mr1];
            if (mr0 >= 2048) t0 = copysignf(fmaxf(fabsf(t0) - THRS, 0.f), t0);
            if (mr1 >= 2048) t1 = copysignf(fmaxf(fabsf(t1) - THRS, 0.f), t1);
            split2(t0, t1, h[j], l[j]);
        }
        size_t off = ((size_t)b*FF + c)*M1 + m0 + mb;
        *(uint4*)(g_xsT_h + off)     = make_uint4(h[0], h[1], h[2], h[3]);
        *(uint4*)(g_xsT_h + off + 8) = make_uint4(h[4], h[5], h[6], h[7]);
        *(uint4*)(g_xsT_l + off)     = make_uint4(l[0], l[1], l[2], l[3]);
        *(uint4*)(g_xsT_l + off + 8) = make_uint4(l[4], l[5], l[6], l[7]);
    } else {
        int g0 = m0 + r0, g1 = g0 + 8;
        float* base = g_part + (size_t)ks*TOTC + (size_t)b*KO*FF;
#pragma unroll
        for (int nt = 0; nt < 4; nt++){
            int c0 = nt*8 + 2*tg;
            if (g0 < KO) *(float2*)(base + (size_t)g0*FF + c0) = make_float2(acc[nt][0], acc[nt][1]);
            if (g1 < KO) *(float2*)(base + (size_t)g1*FF + c0) = make_float2(acc[nt][2], acc[nt][3]);
        }
    }
}

// ---------- combine split-K partials + bias ----------
__global__ void k_combine(const float* __restrict__ bias, float* __restrict__ out){
    int idx = blockIdx.x*NTHR + threadIdx.x;
    if (idx < TOTC){
        float s = bias[idx & 31];
        s += g_part[idx];
        s += g_part[TOTC + idx];
        s += g_part[2*TOTC + idx];
        s += g_part[3*TOTC + idx];
        out[idx] = s;
    }
}

extern "C" void kernel_launch(void* const* d_in, const int* in_sizes, int n_in,
                              void* d_out, int out_size){
    (void)in_sizes; (void)n_in; (void)out_size;
    const float* x    = (const float*)d_in[0];
    const float* dl   = (const float*)d_in[1];
    const float* w    = (const float*)d_in[2];
    const float* filt = (const float*)d_in[3];
    const float* bias = (const float*)d_in[4];
    float* out = (float*)d_out;

    k_xw<<<64, NTHR>>>(x, w);
    k_gemm<false><<<96, NTHR>>>(dl, filt);
    k_gemm<true><<<136, NTHR>>>(dl, nullptr);
    k_combine<<<(TOTC + NTHR - 1)/NTHR, NTHR>>>(bias, out);
}